// round 1
// baseline (speedup 1.0000x reference)
#include <cuda_runtime.h>
#include <cstdint>
#include <cstddef>

#define S_LEN 2048
#define HID   4096
#define NH    32
#define HD    128
#define P3    12288   // 3*HID

// ---------------- scratch (no allocations allowed) ----------------
__device__ float g_proj[S_LEN * P3];   // QKV after projection (RoPE applied in-place)
__device__ float g_attn[S_LEN * HID];  // attention output, [s, h*128+d] layout

// ---------------- f32x2 helpers (FFMA2 path, sm_100+) ----------------
__device__ __forceinline__ unsigned long long pack2(float x, float y) {
    unsigned long long r;
    asm("mov.b64 %0, {%1,%2};" : "=l"(r) : "f"(x), "f"(y));
    return r;
}
__device__ __forceinline__ void ffma2(unsigned long long& d, unsigned long long a,
                                      unsigned long long b) {
    asm("fma.rn.f32x2 %0, %1, %2, %0;" : "+l"(d) : "l"(a), "l"(b));
}
__device__ __forceinline__ void fmul2(unsigned long long& d, unsigned long long a) {
    asm("mul.rn.f32x2 %0, %0, %1;" : "+l"(d) : "l"(a));
}
__device__ __forceinline__ float2 unpack2(unsigned long long v) {
    float2 r;
    asm("mov.b64 {%0,%1}, %2;" : "=f"(r.x), "=f"(r.y) : "l"(v));
    return r;
}

// ---------------- SGEMM: C[M,N] = A[M,K] * B[N,K]^T (all row-major) ----------------
// 128x128x16 block tile, 256 threads, 8x8 per thread, double-buffered smem,
// f32x2 packed accumulation. Thread owns cols n0 + 2*tx + 32*j (+0/1)  -> conflict-free
// 64-bit B loads (16 lanes cover all 32 banks).
__global__ __launch_bounds__(256, 1) void sgemm_tn(const float* __restrict__ A,
                                                   const float* __restrict__ B,
                                                   float* __restrict__ C,
                                                   int M, int N, int K) {
    __shared__ float As[2][16][128];
    __shared__ float Bs[2][16][128];

    const int t  = threadIdx.x;
    const int tx = t & 15, ty = t >> 4;
    const int m0 = blockIdx.y * 128, n0 = blockIdx.x * 128;
    const float* Ab = A + (size_t)m0 * K;
    const float* Bb = B + (size_t)n0 * K;

    const int r0 = t >> 2;        // 0..63
    const int r1 = r0 + 64;       // 64..127
    const int kq = (t & 3) * 4;   // 0,4,8,12

    // prologue: load tile 0
    float4 a0g = *(const float4*)&Ab[(size_t)r0 * K + kq];
    float4 a1g = *(const float4*)&Ab[(size_t)r1 * K + kq];
    float4 b0g = *(const float4*)&Bb[(size_t)r0 * K + kq];
    float4 b1g = *(const float4*)&Bb[(size_t)r1 * K + kq];
    As[0][kq+0][r0]=a0g.x; As[0][kq+1][r0]=a0g.y; As[0][kq+2][r0]=a0g.z; As[0][kq+3][r0]=a0g.w;
    As[0][kq+0][r1]=a1g.x; As[0][kq+1][r1]=a1g.y; As[0][kq+2][r1]=a1g.z; As[0][kq+3][r1]=a1g.w;
    Bs[0][kq+0][r0]=b0g.x; Bs[0][kq+1][r0]=b0g.y; Bs[0][kq+2][r0]=b0g.z; Bs[0][kq+3][r0]=b0g.w;
    Bs[0][kq+0][r1]=b1g.x; Bs[0][kq+1][r1]=b1g.y; Bs[0][kq+2][r1]=b1g.z; Bs[0][kq+3][r1]=b1g.w;
    __syncthreads();

    unsigned long long acc[8][4];
#pragma unroll
    for (int i = 0; i < 8; i++)
#pragma unroll
        for (int j = 0; j < 4; j++) acc[i][j] = 0ull;

    const int nk = K >> 4;
    for (int kt = 0; kt < nk; kt++) {
        const int cur = kt & 1;
        const bool has_next = (kt + 1 < nk);
        float4 na0, na1, nb0, nb1;
        if (has_next) {
            size_t ko = (size_t)(kt + 1) * 16 + kq;
            na0 = *(const float4*)&Ab[(size_t)r0 * K + ko];
            na1 = *(const float4*)&Ab[(size_t)r1 * K + ko];
            nb0 = *(const float4*)&Bb[(size_t)r0 * K + ko];
            nb1 = *(const float4*)&Bb[(size_t)r1 * K + ko];
        }
#pragma unroll
        for (int k = 0; k < 16; k++) {
            float4 av0 = *(const float4*)&As[cur][k][ty * 8];
            float4 av1 = *(const float4*)&As[cur][k][ty * 8 + 4];
            unsigned long long bp[4];
#pragma unroll
            for (int j = 0; j < 4; j++)
                bp[j] = *(const unsigned long long*)&Bs[cur][k][2 * tx + 32 * j];
            float av[8] = {av0.x, av0.y, av0.z, av0.w, av1.x, av1.y, av1.z, av1.w};
#pragma unroll
            for (int i = 0; i < 8; i++) {
                unsigned long long ap = pack2(av[i], av[i]);
#pragma unroll
                for (int j = 0; j < 4; j++) ffma2(acc[i][j], ap, bp[j]);
            }
        }
        if (has_next) {
            const int nxt = cur ^ 1;
            As[nxt][kq+0][r0]=na0.x; As[nxt][kq+1][r0]=na0.y; As[nxt][kq+2][r0]=na0.z; As[nxt][kq+3][r0]=na0.w;
            As[nxt][kq+0][r1]=na1.x; As[nxt][kq+1][r1]=na1.y; As[nxt][kq+2][r1]=na1.z; As[nxt][kq+3][r1]=na1.w;
            Bs[nxt][kq+0][r0]=nb0.x; Bs[nxt][kq+1][r0]=nb0.y; Bs[nxt][kq+2][r0]=nb0.z; Bs[nxt][kq+3][r0]=nb0.w;
            Bs[nxt][kq+0][r1]=nb1.x; Bs[nxt][kq+1][r1]=nb1.y; Bs[nxt][kq+2][r1]=nb1.z; Bs[nxt][kq+3][r1]=nb1.w;
        }
        __syncthreads();
    }

#pragma unroll
    for (int i = 0; i < 8; i++) {
        size_t cro = (size_t)(m0 + ty * 8 + i) * N + n0 + 2 * tx;
#pragma unroll
        for (int j = 0; j < 4; j++) {
            float2 f = unpack2(acc[i][j]);
            *(float2*)&C[cro + 32 * j] = f;
        }
    }
}

// ---------------- RoPE (in-place on g_proj, Q and K) ----------------
__global__ void rope_kernel(float* __restrict__ proj, const int* __restrict__ pos_ids) {
    int idx = blockIdx.x * blockDim.x + threadIdx.x;   // S*NH*64 threads
    if (idx >= S_LEN * NH * 64) return;
    int d = idx & 63;
    int h = (idx >> 6) & 31;
    int s = idx >> 11;
    int pos = pos_ids[s];

    // angle = pos / 10000^(d/64), computed in fp64, reduced mod 2pi
    double inv = exp(-((double)d / 64.0) * 9.210340371976184);  // ln(10000)
    double a = (double)pos * inv;
    const double twopi = 6.283185307179586476925286766559;
    a -= floor(a / twopi) * twopi;
    float sa, ca;
    __sincosf((float)a, &sa, &ca);  // arg in [0, 2pi): fast path accurate here
    // use accurate sin/cos instead (arg small, full accuracy):
    sa = sinf((float)a);
    ca = cosf((float)a);

    size_t base = (size_t)s * P3 + h * HD;
    float q1 = proj[base + d], q2 = proj[base + d + 64];
    proj[base + d]      = q1 * ca - q2 * sa;
    proj[base + d + 64] = q2 * ca + q1 * sa;
    size_t kb = base + HID;
    float k1 = proj[kb + d], k2 = proj[kb + d + 64];
    proj[kb + d]      = k1 * ca - k2 * sa;
    proj[kb + d + 64] = k2 * ca + k1 * sa;
}

// ---------------- Flash attention (fp32, causal, online softmax) ----------------
// grid = (NH, 32 q-tiles, launched heaviest-first), 256 threads.
// Tiles: 64 q-rows x 64 k-cols x 128 dims. f32x2-packed score & PV loops.
#define SROW 130   // padded smem row stride (floats) for Q/K/V: conflict-free strided access
#define ATTN_SMEM ((3 * 64 * SROW + 64 * 65 + 3 * 64) * 4)

__global__ __launch_bounds__(256, 1) void attn_kernel(const float* __restrict__ proj,
                                                      float* __restrict__ attn_out) {
    extern __shared__ float sm[];
    float* Qs   = sm;                 // 64 x SROW
    float* Ks   = Qs + 64 * SROW;
    float* Vs   = Ks + 64 * SROW;
    float* Ps   = Vs + 64 * SROW;     // 64 x 65
    float* rowM = Ps + 64 * 65;
    float* rowL = rowM + 64;
    float* rowA = rowL + 64;

    const int t  = threadIdx.x;
    const int h  = blockIdx.x;
    const int qt = (int)gridDim.y - 1 - (int)blockIdx.y;  // heavy tiles first
    const int qcol = h * HD;
    const int kcol = HID + h * HD;
    const int vcol = 2 * HID + h * HD;

    const int lr = t >> 5;            // load row group
    const int lc = (t & 31) * 4;      // load col

    // load Q tile
#pragma unroll
    for (int it = 0; it < 8; it++) {
        int r = lr + it * 8;
        float4 v = *(const float4*)&proj[(size_t)(qt * 64 + r) * P3 + qcol + lc];
        float* dst = &Qs[r * SROW + lc];
        dst[0]=v.x; dst[1]=v.y; dst[2]=v.z; dst[3]=v.w;
    }
    if (t < 64) { rowM[t] = -3.0e38f; rowL[t] = 0.f; }

    const int sx = t & 15, sy = t >> 4;
    // thread owns q-rows sy*4+i ; score cols sx+16*j ; output dims 2*sx+32*j(+1)
    unsigned long long o2[4][4];
#pragma unroll
    for (int i = 0; i < 4; i++)
#pragma unroll
        for (int j = 0; j < 4; j++) o2[i][j] = 0ull;

    for (int kt = 0; kt <= qt; kt++) {
        __syncthreads();
        // load K,V tiles
#pragma unroll
        for (int it = 0; it < 8; it++) {
            int r = lr + it * 8;
            size_t grow = (size_t)(kt * 64 + r) * P3;
            float4 kv = *(const float4*)&proj[grow + kcol + lc];
            float* dk = &Ks[r * SROW + lc];
            dk[0]=kv.x; dk[1]=kv.y; dk[2]=kv.z; dk[3]=kv.w;
            float4 vv = *(const float4*)&proj[grow + vcol + lc];
            float* dv = &Vs[r * SROW + lc];
            dv[0]=vv.x; dv[1]=vv.y; dv[2]=vv.z; dv[3]=vv.w;
        }
        __syncthreads();

        // scores: 4x4 per thread, f32x2 along d
        unsigned long long sc[4][4];
#pragma unroll
        for (int i = 0; i < 4; i++)
#pragma unroll
            for (int j = 0; j < 4; j++) sc[i][j] = 0ull;
#pragma unroll 8
        for (int d = 0; d < HD; d += 2) {
            unsigned long long qp[4], kp[4];
#pragma unroll
            for (int i = 0; i < 4; i++)
                qp[i] = *(const unsigned long long*)&Qs[(sy * 4 + i) * SROW + d];
#pragma unroll
            for (int j = 0; j < 4; j++)
                kp[j] = *(const unsigned long long*)&Ks[(sx + 16 * j) * SROW + d];
#pragma unroll
            for (int i = 0; i < 4; i++)
#pragma unroll
                for (int j = 0; j < 4; j++) ffma2(sc[i][j], qp[i], kp[j]);
        }
        const bool diag = (kt == qt);
#pragma unroll
        for (int i = 0; i < 4; i++) {
#pragma unroll
            for (int j = 0; j < 4; j++) {
                float2 f = unpack2(sc[i][j]);
                float s = (f.x + f.y) * 0.08838834764831845f;  // 1/sqrt(128)
                int col = sx + 16 * j;
                if (diag && col > sy * 4 + i) s = -1.0e9f;     // causal mask (matches ref NEG_INF)
                Ps[(sy * 4 + i) * 65 + col] = s;
            }
        }
        __syncthreads();

        // online softmax: one thread per row
        if (t < 64) {
            float* pr = &Ps[t * 65];
            float m = rowM[t];
#pragma unroll 8
            for (int k = 0; k < 64; k++) m = fmaxf(m, pr[k]);
            float alpha = __expf(rowM[t] - m);
            float ssum = 0.f;
#pragma unroll 8
            for (int k = 0; k < 64; k++) { float p = __expf(pr[k] - m); pr[k] = p; ssum += p; }
            rowL[t] = rowL[t] * alpha + ssum;
            rowM[t] = m;
            rowA[t] = alpha;
        }
        __syncthreads();

        // rescale accumulators, then O += P*V
#pragma unroll
        for (int i = 0; i < 4; i++) {
            float al = rowA[sy * 4 + i];
            unsigned long long al2 = pack2(al, al);
#pragma unroll
            for (int j = 0; j < 4; j++) fmul2(o2[i][j], al2);
        }
#pragma unroll 4
        for (int k = 0; k < 64; k++) {
            unsigned long long vp[4];
#pragma unroll
            for (int j = 0; j < 4; j++)
                vp[j] = *(const unsigned long long*)&Vs[k * SROW + 2 * sx + 32 * j];
#pragma unroll
            for (int i = 0; i < 4; i++) {
                float p = Ps[(sy * 4 + i) * 65 + k];
                unsigned long long p2 = pack2(p, p);
#pragma unroll
                for (int j = 0; j < 4; j++) ffma2(o2[i][j], p2, vp[j]);
            }
        }
    }

    // epilogue: divide by l, write [s, h*128 + d]
#pragma unroll
    for (int i = 0; i < 4; i++) {
        int r = sy * 4 + i;
        float inv = 1.0f / rowL[r];
        unsigned long long inv2 = pack2(inv, inv);
        size_t orow = (size_t)(qt * 64 + r) * HID + h * HD + 2 * sx;
#pragma unroll
        for (int j = 0; j < 4; j++) {
            fmul2(o2[i][j], inv2);
            float2 f = unpack2(o2[i][j]);
            *(float2*)&attn_out[orow + 32 * j] = f;
        }
    }
}

// ---------------- launch ----------------
extern "C" void kernel_launch(void* const* d_in, const int* in_sizes, int n_in,
                              void* d_out, int out_size) {
    (void)in_sizes; (void)n_in; (void)out_size;
    const float* hidden  = (const float*)d_in[0];
    // d_in[1] = attention_mask: deterministic causal -> applied analytically
    const int*   pos_ids = (const int*)d_in[2];
    const float* W_pack  = (const float*)d_in[3];
    const float* W_o     = (const float*)d_in[4];
    float* out = (float*)d_out;

    float *proj = nullptr, *attn = nullptr;
    cudaGetSymbolAddress((void**)&proj, g_proj);
    cudaGetSymbolAddress((void**)&attn, g_attn);
    cudaFuncSetAttribute(attn_kernel, cudaFuncAttributeMaxDynamicSharedMemorySize, ATTN_SMEM);

    // 1) QKV projection: [2048,4096] @ [12288,4096]^T
    sgemm_tn<<<dim3(P3 / 128, S_LEN / 128), 256>>>(hidden, W_pack, proj, S_LEN, P3, HID);
    // 2) RoPE in-place on Q,K
    rope_kernel<<<(S_LEN * NH * 64) / 256, 256>>>(proj, pos_ids);
    // 3) causal flash attention
    attn_kernel<<<dim3(NH, S_LEN / 64), 256, ATTN_SMEM>>>(proj, attn);
    // 4) output projection: [2048,4096] @ [4096,4096]^T
    sgemm_tn<<<dim3(HID / 128, S_LEN / 128), 256>>>(attn, W_o, out, S_LEN, HID, HID);
}

// round 2
// speedup vs baseline: 1.0012x; 1.0012x over previous
#include <cuda_runtime.h>
#include <cstdint>
#include <cstddef>

#define S_LEN 2048
#define HID   4096
#define NH    32
#define HD    128
#define P3    12288   // 3*HID

// ---------------- scratch (no allocations allowed) ----------------
__device__ float g_proj[S_LEN * P3];   // QKV after projection (RoPE applied in-place)
__device__ float g_attn[S_LEN * HID];  // attention output, [s, h*128+d] layout

// ---------------- f32x2 helpers (FFMA2 path, sm_100+) ----------------
__device__ __forceinline__ unsigned long long pack2(float x, float y) {
    unsigned long long r;
    asm("mov.b64 %0, {%1,%2};" : "=l"(r) : "f"(x), "f"(y));
    return r;
}
__device__ __forceinline__ void ffma2(unsigned long long& d, unsigned long long a,
                                      unsigned long long b) {
    asm("fma.rn.f32x2 %0, %1, %2, %0;" : "+l"(d) : "l"(a), "l"(b));
}
__device__ __forceinline__ void fmul2(unsigned long long& d, unsigned long long a) {
    asm("mul.rn.f32x2 %0, %0, %1;" : "+l"(d) : "l"(a));
}
__device__ __forceinline__ float2 unpack2(unsigned long long v) {
    float2 r;
    asm("mov.b64 {%0,%1}, %2;" : "=f"(r.x), "=f"(r.y) : "l"(v));
    return r;
}

// ---------------- SGEMM: C[M,N] = A[M,K] * B[N,K]^T (all row-major) ----------------
// 128x128x16 block tile, 256 threads, 8x8 per thread, double-buffered smem,
// f32x2 packed accumulation. Thread owns cols n0 + 2*tx + 32*j (+0/1)  -> conflict-free
// 64-bit B loads (16 lanes cover all 32 banks).
__global__ __launch_bounds__(256, 1) void sgemm_tn(const float* __restrict__ A,
                                                   const float* __restrict__ B,
                                                   float* __restrict__ C,
                                                   int M, int N, int K) {
    __shared__ float As[2][16][128];
    __shared__ float Bs[2][16][128];

    const int t  = threadIdx.x;
    const int tx = t & 15, ty = t >> 4;
    const int m0 = blockIdx.y * 128, n0 = blockIdx.x * 128;
    const float* Ab = A + (size_t)m0 * K;
    const float* Bb = B + (size_t)n0 * K;

    const int r0 = t >> 2;        // 0..63
    const int r1 = r0 + 64;       // 64..127
    const int kq = (t & 3) * 4;   // 0,4,8,12

    // prologue: load tile 0
    float4 a0g = *(const float4*)&Ab[(size_t)r0 * K + kq];
    float4 a1g = *(const float4*)&Ab[(size_t)r1 * K + kq];
    float4 b0g = *(const float4*)&Bb[(size_t)r0 * K + kq];
    float4 b1g = *(const float4*)&Bb[(size_t)r1 * K + kq];
    As[0][kq+0][r0]=a0g.x; As[0][kq+1][r0]=a0g.y; As[0][kq+2][r0]=a0g.z; As[0][kq+3][r0]=a0g.w;
    As[0][kq+0][r1]=a1g.x; As[0][kq+1][r1]=a1g.y; As[0][kq+2][r1]=a1g.z; As[0][kq+3][r1]=a1g.w;
    Bs[0][kq+0][r0]=b0g.x; Bs[0][kq+1][r0]=b0g.y; Bs[0][kq+2][r0]=b0g.z; Bs[0][kq+3][r0]=b0g.w;
    Bs[0][kq+0][r1]=b1g.x; Bs[0][kq+1][r1]=b1g.y; Bs[0][kq+2][r1]=b1g.z; Bs[0][kq+3][r1]=b1g.w;
    __syncthreads();

    unsigned long long acc[8][4];
#pragma unroll
    for (int i = 0; i < 8; i++)
#pragma unroll
        for (int j = 0; j < 4; j++) acc[i][j] = 0ull;

    const int nk = K >> 4;
    for (int kt = 0; kt < nk; kt++) {
        const int cur = kt & 1;
        const bool has_next = (kt + 1 < nk);
        float4 na0, na1, nb0, nb1;
        if (has_next) {
            size_t ko = (size_t)(kt + 1) * 16 + kq;
            na0 = *(const float4*)&Ab[(size_t)r0 * K + ko];
            na1 = *(const float4*)&Ab[(size_t)r1 * K + ko];
            nb0 = *(const float4*)&Bb[(size_t)r0 * K + ko];
            nb1 = *(const float4*)&Bb[(size_t)r1 * K + ko];
        }
#pragma unroll
        for (int k = 0; k < 16; k++) {
            float4 av0 = *(const float4*)&As[cur][k][ty * 8];
            float4 av1 = *(const float4*)&As[cur][k][ty * 8 + 4];
            unsigned long long bp[4];
#pragma unroll
            for (int j = 0; j < 4; j++)
                bp[j] = *(const unsigned long long*)&Bs[cur][k][2 * tx + 32 * j];
            float av[8] = {av0.x, av0.y, av0.z, av0.w, av1.x, av1.y, av1.z, av1.w};
#pragma unroll
            for (int i = 0; i < 8; i++) {
                unsigned long long ap = pack2(av[i], av[i]);
#pragma unroll
                for (int j = 0; j < 4; j++) ffma2(acc[i][j], ap, bp[j]);
            }
        }
        if (has_next) {
            const int nxt = cur ^ 1;
            As[nxt][kq+0][r0]=na0.x; As[nxt][kq+1][r0]=na0.y; As[nxt][kq+2][r0]=na0.z; As[nxt][kq+3][r0]=na0.w;
            As[nxt][kq+0][r1]=na1.x; As[nxt][kq+1][r1]=na1.y; As[nxt][kq+2][r1]=na1.z; As[nxt][kq+3][r1]=na1.w;
            Bs[nxt][kq+0][r0]=nb0.x; Bs[nxt][kq+1][r0]=nb0.y; Bs[nxt][kq+2][r0]=nb0.z; Bs[nxt][kq+3][r0]=nb0.w;
            Bs[nxt][kq+0][r1]=nb1.x; Bs[nxt][kq+1][r1]=nb1.y; Bs[nxt][kq+2][r1]=nb1.z; Bs[nxt][kq+3][r1]=nb1.w;
        }
        __syncthreads();
    }

#pragma unroll
    for (int i = 0; i < 8; i++) {
        size_t cro = (size_t)(m0 + ty * 8 + i) * N + n0 + 2 * tx;
#pragma unroll
        for (int j = 0; j < 4; j++) {
            float2 f = unpack2(acc[i][j]);
            *(float2*)&C[cro + 32 * j] = f;
        }
    }
}

// ---------------- RoPE (in-place on g_proj, Q and K) ----------------
__global__ void rope_kernel(float* __restrict__ proj, const int* __restrict__ pos_ids) {
    int idx = blockIdx.x * blockDim.x + threadIdx.x;   // S*NH*64 threads
    if (idx >= S_LEN * NH * 64) return;
    int d = idx & 63;
    int h = (idx >> 6) & 31;
    int s = idx >> 11;
    int pos = pos_ids[s];

    // angle = pos / 10000^(d/64), computed in fp64, reduced mod 2pi
    double inv = exp(-((double)d / 64.0) * 9.210340371976184);  // ln(10000)
    double a = (double)pos * inv;
    const double twopi = 6.283185307179586476925286766559;
    a -= floor(a / twopi) * twopi;
    float sa, ca;
    __sincosf((float)a, &sa, &ca);  // arg in [0, 2pi): fast path accurate here
    // use accurate sin/cos instead (arg small, full accuracy):
    sa = sinf((float)a);
    ca = cosf((float)a);

    size_t base = (size_t)s * P3 + h * HD;
    float q1 = proj[base + d], q2 = proj[base + d + 64];
    proj[base + d]      = q1 * ca - q2 * sa;
    proj[base + d + 64] = q2 * ca + q1 * sa;
    size_t kb = base + HID;
    float k1 = proj[kb + d], k2 = proj[kb + d + 64];
    proj[kb + d]      = k1 * ca - k2 * sa;
    proj[kb + d + 64] = k2 * ca + k1 * sa;
}

// ---------------- Flash attention (fp32, causal, online softmax) ----------------
// grid = (NH, 32 q-tiles, launched heaviest-first), 256 threads.
// Tiles: 64 q-rows x 64 k-cols x 128 dims. f32x2-packed score & PV loops.
#define SROW 130   // padded smem row stride (floats) for Q/K/V: conflict-free strided access
#define ATTN_SMEM ((3 * 64 * SROW + 64 * 65 + 3 * 64) * 4)

__global__ __launch_bounds__(256, 1) void attn_kernel(const float* __restrict__ proj,
                                                      float* __restrict__ attn_out) {
    extern __shared__ float sm[];
    float* Qs   = sm;                 // 64 x SROW
    float* Ks   = Qs + 64 * SROW;
    float* Vs   = Ks + 64 * SROW;
    float* Ps   = Vs + 64 * SROW;     // 64 x 65
    float* rowM = Ps + 64 * 65;
    float* rowL = rowM + 64;
    float* rowA = rowL + 64;

    const int t  = threadIdx.x;
    const int h  = blockIdx.x;
    const int qt = (int)gridDim.y - 1 - (int)blockIdx.y;  // heavy tiles first
    const int qcol = h * HD;
    const int kcol = HID + h * HD;
    const int vcol = 2 * HID + h * HD;

    const int lr = t >> 5;            // load row group
    const int lc = (t & 31) * 4;      // load col

    // load Q tile
#pragma unroll
    for (int it = 0; it < 8; it++) {
        int r = lr + it * 8;
        float4 v = *(const float4*)&proj[(size_t)(qt * 64 + r) * P3 + qcol + lc];
        float* dst = &Qs[r * SROW + lc];
        dst[0]=v.x; dst[1]=v.y; dst[2]=v.z; dst[3]=v.w;
    }
    if (t < 64) { rowM[t] = -3.0e38f; rowL[t] = 0.f; }

    const int sx = t & 15, sy = t >> 4;
    // thread owns q-rows sy*4+i ; score cols sx+16*j ; output dims 2*sx+32*j(+1)
    unsigned long long o2[4][4];
#pragma unroll
    for (int i = 0; i < 4; i++)
#pragma unroll
        for (int j = 0; j < 4; j++) o2[i][j] = 0ull;

    for (int kt = 0; kt <= qt; kt++) {
        __syncthreads();
        // load K,V tiles
#pragma unroll
        for (int it = 0; it < 8; it++) {
            int r = lr + it * 8;
            size_t grow = (size_t)(kt * 64 + r) * P3;
            float4 kv = *(const float4*)&proj[grow + kcol + lc];
            float* dk = &Ks[r * SROW + lc];
            dk[0]=kv.x; dk[1]=kv.y; dk[2]=kv.z; dk[3]=kv.w;
            float4 vv = *(const float4*)&proj[grow + vcol + lc];
            float* dv = &Vs[r * SROW + lc];
            dv[0]=vv.x; dv[1]=vv.y; dv[2]=vv.z; dv[3]=vv.w;
        }
        __syncthreads();

        // scores: 4x4 per thread, f32x2 along d
        unsigned long long sc[4][4];
#pragma unroll
        for (int i = 0; i < 4; i++)
#pragma unroll
            for (int j = 0; j < 4; j++) sc[i][j] = 0ull;
#pragma unroll 8
        for (int d = 0; d < HD; d += 2) {
            unsigned long long qp[4], kp[4];
#pragma unroll
            for (int i = 0; i < 4; i++)
                qp[i] = *(const unsigned long long*)&Qs[(sy * 4 + i) * SROW + d];
#pragma unroll
            for (int j = 0; j < 4; j++)
                kp[j] = *(const unsigned long long*)&Ks[(sx + 16 * j) * SROW + d];
#pragma unroll
            for (int i = 0; i < 4; i++)
#pragma unroll
                for (int j = 0; j < 4; j++) ffma2(sc[i][j], qp[i], kp[j]);
        }
        const bool diag = (kt == qt);
#pragma unroll
        for (int i = 0; i < 4; i++) {
#pragma unroll
            for (int j = 0; j < 4; j++) {
                float2 f = unpack2(sc[i][j]);
                float s = (f.x + f.y) * 0.08838834764831845f;  // 1/sqrt(128)
                int col = sx + 16 * j;
                if (diag && col > sy * 4 + i) s = -1.0e9f;     // causal mask (matches ref NEG_INF)
                Ps[(sy * 4 + i) * 65 + col] = s;
            }
        }
        __syncthreads();

        // online softmax: one thread per row
        if (t < 64) {
            float* pr = &Ps[t * 65];
            float m = rowM[t];
#pragma unroll 8
            for (int k = 0; k < 64; k++) m = fmaxf(m, pr[k]);
            float alpha = __expf(rowM[t] - m);
            float ssum = 0.f;
#pragma unroll 8
            for (int k = 0; k < 64; k++) { float p = __expf(pr[k] - m); pr[k] = p; ssum += p; }
            rowL[t] = rowL[t] * alpha + ssum;
            rowM[t] = m;
            rowA[t] = alpha;
        }
        __syncthreads();

        // rescale accumulators, then O += P*V
#pragma unroll
        for (int i = 0; i < 4; i++) {
            float al = rowA[sy * 4 + i];
            unsigned long long al2 = pack2(al, al);
#pragma unroll
            for (int j = 0; j < 4; j++) fmul2(o2[i][j], al2);
        }
#pragma unroll 4
        for (int k = 0; k < 64; k++) {
            unsigned long long vp[4];
#pragma unroll
            for (int j = 0; j < 4; j++)
                vp[j] = *(const unsigned long long*)&Vs[k * SROW + 2 * sx + 32 * j];
#pragma unroll
            for (int i = 0; i < 4; i++) {
                float p = Ps[(sy * 4 + i) * 65 + k];
                unsigned long long p2 = pack2(p, p);
#pragma unroll
                for (int j = 0; j < 4; j++) ffma2(o2[i][j], p2, vp[j]);
            }
        }
    }

    // epilogue: divide by l, write [s, h*128 + d]
#pragma unroll
    for (int i = 0; i < 4; i++) {
        int r = sy * 4 + i;
        float inv = 1.0f / rowL[r];
        unsigned long long inv2 = pack2(inv, inv);
        size_t orow = (size_t)(qt * 64 + r) * HID + h * HD + 2 * sx;
#pragma unroll
        for (int j = 0; j < 4; j++) {
            fmul2(o2[i][j], inv2);
            float2 f = unpack2(o2[i][j]);
            *(float2*)&attn_out[orow + 32 * j] = f;
        }
    }
}

// ---------------- launch ----------------
extern "C" void kernel_launch(void* const* d_in, const int* in_sizes, int n_in,
                              void* d_out, int out_size) {
    (void)in_sizes; (void)n_in; (void)out_size;
    const float* hidden  = (const float*)d_in[0];
    // d_in[1] = attention_mask: deterministic causal -> applied analytically
    const int*   pos_ids = (const int*)d_in[2];
    const float* W_pack  = (const float*)d_in[3];
    const float* W_o     = (const float*)d_in[4];
    float* out = (float*)d_out;

    float *proj = nullptr, *attn = nullptr;
    cudaGetSymbolAddress((void**)&proj, g_proj);
    cudaGetSymbolAddress((void**)&attn, g_attn);
    cudaFuncSetAttribute(attn_kernel, cudaFuncAttributeMaxDynamicSharedMemorySize, ATTN_SMEM);

    // 1) QKV projection: [2048,4096] @ [12288,4096]^T
    sgemm_tn<<<dim3(P3 / 128, S_LEN / 128), 256>>>(hidden, W_pack, proj, S_LEN, P3, HID);
    // 2) RoPE in-place on Q,K
    rope_kernel<<<(S_LEN * NH * 64) / 256, 256>>>(proj, pos_ids);
    // 3) causal flash attention
    attn_kernel<<<dim3(NH, S_LEN / 64), 256, ATTN_SMEM>>>(proj, attn);
    // 4) output projection: [2048,4096] @ [4096,4096]^T
    sgemm_tn<<<dim3(HID / 128, S_LEN / 128), 256>>>(attn, W_o, out, S_LEN, HID, HID);
}

// round 4
// speedup vs baseline: 2.5894x; 2.5862x over previous
#include <cuda_runtime.h>
#include <cstdint>
#include <cstddef>

#define S_LEN 2048
#define HID   4096
#define NH    32
#define HD    128
#define P3    12288   // 3*HID

// ---------------- scratch (no allocations allowed) ----------------
__device__ float g_proj[S_LEN * P3];   // QKV after projection (RoPE applied in-place)
__device__ float g_attn[S_LEN * HID];  // attention output, [s, h*128+d] layout

// ---------------- f32x2 helpers ----------------
__device__ __forceinline__ unsigned long long pack2(float x, float y) {
    unsigned long long r;
    asm("mov.b64 %0, {%1,%2};" : "=l"(r) : "f"(x), "f"(y));
    return r;
}
__device__ __forceinline__ void ffma2(unsigned long long& d, unsigned long long a,
                                      unsigned long long b) {
    asm("fma.rn.f32x2 %0, %1, %2, %0;" : "+l"(d) : "l"(a), "l"(b));
}
__device__ __forceinline__ void fmul2(unsigned long long& d, unsigned long long a) {
    asm("mul.rn.f32x2 %0, %0, %1;" : "+l"(d) : "l"(a));
}
__device__ __forceinline__ float2 unpack2(unsigned long long v) {
    float2 r;
    asm("mov.b64 {%0,%1}, %2;" : "=f"(r.x), "=f"(r.y) : "l"(v));
    return r;
}
__device__ __forceinline__ uint32_t f2tf32(float x) {
    uint32_t r;
    asm("cvt.rna.tf32.f32 %0, %1;" : "=r"(r) : "f"(x));
    return r;
}

// mma.sync m16n8k8 tf32 (base ISA, works on compute_103 / fallback HMMA path)
__device__ __forceinline__ void mma_tf32(float& c0, float& c1, float& c2, float& c3,
                                         uint32_t a0, uint32_t a1, uint32_t a2, uint32_t a3,
                                         uint32_t b0, uint32_t b1) {
    asm volatile(
        "mma.sync.aligned.m16n8k8.row.col.f32.tf32.tf32.f32 "
        "{%0,%1,%2,%3}, {%4,%5,%6,%7}, {%8,%9}, {%0,%1,%2,%3};"
        : "+f"(c0), "+f"(c1), "+f"(c2), "+f"(c3)
        : "r"(a0), "r"(a1), "r"(a2), "r"(a3), "r"(b0), "r"(b1));
}

// ---------------- tf32 mma GEMM: C[M,N] = A[M,K] * B[N,K]^T ----------------
// Block 128x128x32, 256 threads (8 warps), warp tile 64x32.
// SMEM: [row][36] fp32 (stride-36 pad -> conflict-free fragment LDS: bank=(4g+c)%32).
#define GBK    32
#define SROW_G 36
#define GSTG   (128 * SROW_G * 4)          // 18432 B per stage
#define GEMM_SMEM (4 * GSTG)               // A[2] + B[2] = 73728 B

__global__ __launch_bounds__(256, 1) void gemm_tf32mma(const float* __restrict__ A,
                                                       const float* __restrict__ B,
                                                       float* __restrict__ C,
                                                       int M, int N, int K) {
    extern __shared__ float smem[];
    float* As = smem;                       // [2][128][36]
    float* Bs = smem + 2 * 128 * SROW_G;    // [2][128][36]

    const int t = threadIdx.x;
    const int w = t >> 5, lane = t & 31;
    const int wm = w >> 2, wn = w & 3;      // warp grid 2x4 -> 64x32 per warp
    const int g = lane >> 2, cc = lane & 3; // fragment lane decomposition
    const int m0 = blockIdx.y * 128, n0 = blockIdx.x * 128;
    const int KT = K / GBK;

    // global load slots: 128 rows x 32 cols per tile; thread handles row t>>3 (+32i), float4 col t&7
    const int lrow = t >> 3, lc4 = (t & 7) * 4;
    const float* Ab = A + (size_t)(m0 + lrow) * K + lc4;
    const float* Bb = B + (size_t)(n0 + lrow) * K + lc4;
    const size_t rstep = (size_t)32 * K;

    float4 ra[4], rb[4];
#pragma unroll
    for (int i = 0; i < 4; i++) { ra[i] = *(const float4*)(Ab + i * rstep); }
#pragma unroll
    for (int i = 0; i < 4; i++) { rb[i] = *(const float4*)(Bb + i * rstep); }
#pragma unroll
    for (int i = 0; i < 4; i++) {
        uint4 va = {f2tf32(ra[i].x), f2tf32(ra[i].y), f2tf32(ra[i].z), f2tf32(ra[i].w)};
        *(uint4*)&As[(lrow + 32 * i) * SROW_G + lc4] = va;
        uint4 vb = {f2tf32(rb[i].x), f2tf32(rb[i].y), f2tf32(rb[i].z), f2tf32(rb[i].w)};
        *(uint4*)&Bs[(lrow + 32 * i) * SROW_G + lc4] = vb;
    }
    __syncthreads();

    float acc[4][4][4];   // [mt][nt][frag]
#pragma unroll
    for (int mt = 0; mt < 4; mt++)
#pragma unroll
        for (int nt = 0; nt < 4; nt++)
#pragma unroll
            for (int q = 0; q < 4; q++) acc[mt][nt][q] = 0.f;

    for (int kt = 0; kt < KT; kt++) {
        const int cur = kt & 1;
        const bool hasnext = (kt + 1 < KT);
        if (hasnext) {
            const float* Ap = Ab + (size_t)(kt + 1) * GBK;
            const float* Bp = Bb + (size_t)(kt + 1) * GBK;
#pragma unroll
            for (int i = 0; i < 4; i++) ra[i] = *(const float4*)(Ap + i * rstep);
#pragma unroll
            for (int i = 0; i < 4; i++) rb[i] = *(const float4*)(Bp + i * rstep);
        }
        const float* Ac = As + cur * 128 * SROW_G;
        const float* Bc = Bs + cur * 128 * SROW_G;
#pragma unroll
        for (int kc = 0; kc < GBK; kc += 8) {
            uint32_t af[4][4];
#pragma unroll
            for (int mt = 0; mt < 4; mt++) {
                const int r = wm * 64 + mt * 16 + g;
                af[mt][0] = __float_as_uint(Ac[r * SROW_G + kc + cc]);
                af[mt][1] = __float_as_uint(Ac[(r + 8) * SROW_G + kc + cc]);
                af[mt][2] = __float_as_uint(Ac[r * SROW_G + kc + cc + 4]);
                af[mt][3] = __float_as_uint(Ac[(r + 8) * SROW_G + kc + cc + 4]);
            }
            uint32_t bf[4][2];
#pragma unroll
            for (int nt = 0; nt < 4; nt++) {
                const int n = wn * 32 + nt * 8 + g;
                bf[nt][0] = __float_as_uint(Bc[n * SROW_G + kc + cc]);
                bf[nt][1] = __float_as_uint(Bc[n * SROW_G + kc + cc + 4]);
            }
#pragma unroll
            for (int mt = 0; mt < 4; mt++)
#pragma unroll
                for (int nt = 0; nt < 4; nt++)
                    mma_tf32(acc[mt][nt][0], acc[mt][nt][1], acc[mt][nt][2], acc[mt][nt][3],
                             af[mt][0], af[mt][1], af[mt][2], af[mt][3],
                             bf[nt][0], bf[nt][1]);
        }
        __syncthreads();
        if (hasnext) {
            const int nxt = cur ^ 1;
            float* An = As + nxt * 128 * SROW_G;
            float* Bn = Bs + nxt * 128 * SROW_G;
#pragma unroll
            for (int i = 0; i < 4; i++) {
                uint4 va = {f2tf32(ra[i].x), f2tf32(ra[i].y), f2tf32(ra[i].z), f2tf32(ra[i].w)};
                *(uint4*)&An[(lrow + 32 * i) * SROW_G + lc4] = va;
                uint4 vb = {f2tf32(rb[i].x), f2tf32(rb[i].y), f2tf32(rb[i].z), f2tf32(rb[i].w)};
                *(uint4*)&Bn[(lrow + 32 * i) * SROW_G + lc4] = vb;
            }
            __syncthreads();
        }
    }

    // epilogue: c0/c1 at (r, 2cc), (r, 2cc+1); c2/c3 at (r+8, ...)
#pragma unroll
    for (int mt = 0; mt < 4; mt++) {
        const int r = m0 + wm * 64 + mt * 16 + g;
#pragma unroll
        for (int nt = 0; nt < 4; nt++) {
            const int n = n0 + wn * 32 + nt * 8 + 2 * cc;
            *(float2*)&C[(size_t)r * N + n]       = make_float2(acc[mt][nt][0], acc[mt][nt][1]);
            *(float2*)&C[(size_t)(r + 8) * N + n] = make_float2(acc[mt][nt][2], acc[mt][nt][3]);
        }
    }
}

// ---------------- RoPE (in-place on g_proj, Q and K) ----------------
__global__ void rope_kernel(float* __restrict__ proj, const int* __restrict__ pos_ids) {
    int idx = blockIdx.x * blockDim.x + threadIdx.x;   // S*NH*64 threads
    if (idx >= S_LEN * NH * 64) return;
    int d = idx & 63;
    int h = (idx >> 6) & 31;
    int s = idx >> 11;
    int pos = pos_ids[s];

    double inv = exp(-((double)d / 64.0) * 9.210340371976184);  // ln(10000)
    double a = (double)pos * inv;
    const double twopi = 6.283185307179586476925286766559;
    a -= floor(a / twopi) * twopi;
    float sa = sinf((float)a);
    float ca = cosf((float)a);

    size_t base = (size_t)s * P3 + h * HD;
    float q1 = proj[base + d], q2 = proj[base + d + 64];
    proj[base + d]      = q1 * ca - q2 * sa;
    proj[base + d + 64] = q2 * ca + q1 * sa;
    size_t kb = base + HID;
    float k1 = proj[kb + d], k2 = proj[kb + d + 64];
    proj[kb + d]      = k1 * ca - k2 * sa;
    proj[kb + d + 64] = k2 * ca + k1 * sa;
}

// ---------------- Flash attention (fp32, causal, online softmax) ----------------
#define SROW 130
#define ATTN_SMEM ((3 * 64 * SROW + 64 * 65 + 3 * 64) * 4)

__global__ __launch_bounds__(256, 1) void attn_kernel(const float* __restrict__ proj,
                                                      float* __restrict__ attn_out) {
    extern __shared__ float sm[];
    float* Qs   = sm;                 // 64 x SROW
    float* Ks   = Qs + 64 * SROW;
    float* Vs   = Ks + 64 * SROW;
    float* Ps   = Vs + 64 * SROW;     // 64 x 65
    float* rowM = Ps + 64 * 65;
    float* rowL = rowM + 64;
    float* rowA = rowL + 64;

    const int t  = threadIdx.x;
    const int h  = blockIdx.x;
    const int qt = (int)gridDim.y - 1 - (int)blockIdx.y;  // heavy tiles first
    const int qcol = h * HD;
    const int kcol = HID + h * HD;
    const int vcol = 2 * HID + h * HD;

    const int lr = t >> 5;
    const int lc = (t & 31) * 4;

#pragma unroll
    for (int it = 0; it < 8; it++) {
        int r = lr + it * 8;
        float4 v = *(const float4*)&proj[(size_t)(qt * 64 + r) * P3 + qcol + lc];
        float* dst = &Qs[r * SROW + lc];
        dst[0]=v.x; dst[1]=v.y; dst[2]=v.z; dst[3]=v.w;
    }
    if (t < 64) { rowM[t] = -3.0e38f; rowL[t] = 0.f; }

    const int sx = t & 15, sy = t >> 4;
    unsigned long long o2[4][4];
#pragma unroll
    for (int i = 0; i < 4; i++)
#pragma unroll
        for (int j = 0; j < 4; j++) o2[i][j] = 0ull;

    for (int kt = 0; kt <= qt; kt++) {
        __syncthreads();
#pragma unroll
        for (int it = 0; it < 8; it++) {
            int r = lr + it * 8;
            size_t grow = (size_t)(kt * 64 + r) * P3;
            float4 kv = *(const float4*)&proj[grow + kcol + lc];
            float* dk = &Ks[r * SROW + lc];
            dk[0]=kv.x; dk[1]=kv.y; dk[2]=kv.z; dk[3]=kv.w;
            float4 vv = *(const float4*)&proj[grow + vcol + lc];
            float* dv = &Vs[r * SROW + lc];
            dv[0]=vv.x; dv[1]=vv.y; dv[2]=vv.z; dv[3]=vv.w;
        }
        __syncthreads();

        unsigned long long sc[4][4];
#pragma unroll
        for (int i = 0; i < 4; i++)
#pragma unroll
            for (int j = 0; j < 4; j++) sc[i][j] = 0ull;
#pragma unroll 8
        for (int d = 0; d < HD; d += 2) {
            unsigned long long qp[4], kp[4];
#pragma unroll
            for (int i = 0; i < 4; i++)
                qp[i] = *(const unsigned long long*)&Qs[(sy * 4 + i) * SROW + d];
#pragma unroll
            for (int j = 0; j < 4; j++)
                kp[j] = *(const unsigned long long*)&Ks[(sx + 16 * j) * SROW + d];
#pragma unroll
            for (int i = 0; i < 4; i++)
#pragma unroll
                for (int j = 0; j < 4; j++) ffma2(sc[i][j], qp[i], kp[j]);
        }
        const bool diag = (kt == qt);
#pragma unroll
        for (int i = 0; i < 4; i++) {
#pragma unroll
            for (int j = 0; j < 4; j++) {
                float2 f = unpack2(sc[i][j]);
                float s = (f.x + f.y) * 0.08838834764831845f;  // 1/sqrt(128)
                int col = sx + 16 * j;
                if (diag && col > sy * 4 + i) s = -1.0e9f;
                Ps[(sy * 4 + i) * 65 + col] = s;
            }
        }
        __syncthreads();

        if (t < 64) {
            float* pr = &Ps[t * 65];
            float m = rowM[t];
#pragma unroll 8
            for (int k = 0; k < 64; k++) m = fmaxf(m, pr[k]);
            float alpha = __expf(rowM[t] - m);
            float ssum = 0.f;
#pragma unroll 8
            for (int k = 0; k < 64; k++) { float p = __expf(pr[k] - m); pr[k] = p; ssum += p; }
            rowL[t] = rowL[t] * alpha + ssum;
            rowM[t] = m;
            rowA[t] = alpha;
        }
        __syncthreads();

#pragma unroll
        for (int i = 0; i < 4; i++) {
            float al = rowA[sy * 4 + i];
            unsigned long long al2 = pack2(al, al);
#pragma unroll
            for (int j = 0; j < 4; j++) fmul2(o2[i][j], al2);
        }
#pragma unroll 4
        for (int k = 0; k < 64; k++) {
            unsigned long long vp[4];
#pragma unroll
            for (int j = 0; j < 4; j++)
                vp[j] = *(const unsigned long long*)&Vs[k * SROW + 2 * sx + 32 * j];
#pragma unroll
            for (int i = 0; i < 4; i++) {
                float p = Ps[(sy * 4 + i) * 65 + k];
                unsigned long long p2 = pack2(p, p);
#pragma unroll
                for (int j = 0; j < 4; j++) ffma2(o2[i][j], p2, vp[j]);
            }
        }
    }

#pragma unroll
    for (int i = 0; i < 4; i++) {
        int r = sy * 4 + i;
        float inv = 1.0f / rowL[r];
        unsigned long long inv2 = pack2(inv, inv);
        size_t orow = (size_t)(qt * 64 + r) * HID + h * HD + 2 * sx;
#pragma unroll
        for (int j = 0; j < 4; j++) {
            fmul2(o2[i][j], inv2);
            float2 f = unpack2(o2[i][j]);
            *(float2*)&attn_out[orow + 32 * j] = f;
        }
    }
}

// ---------------- launch ----------------
extern "C" void kernel_launch(void* const* d_in, const int* in_sizes, int n_in,
                              void* d_out, int out_size) {
    (void)in_sizes; (void)n_in; (void)out_size;
    const float* hidden  = (const float*)d_in[0];
    // d_in[1] = attention_mask: deterministic causal -> applied analytically
    const int*   pos_ids = (const int*)d_in[2];
    const float* W_pack  = (const float*)d_in[3];
    const float* W_o     = (const float*)d_in[4];
    float* out = (float*)d_out;

    float *proj = nullptr, *attn = nullptr;
    cudaGetSymbolAddress((void**)&proj, g_proj);
    cudaGetSymbolAddress((void**)&attn, g_attn);
    cudaFuncSetAttribute(attn_kernel, cudaFuncAttributeMaxDynamicSharedMemorySize, ATTN_SMEM);
    cudaFuncSetAttribute(gemm_tf32mma, cudaFuncAttributeMaxDynamicSharedMemorySize, GEMM_SMEM);

    // 1) QKV projection: [2048,4096] @ [12288,4096]^T  (tf32 mma)
    gemm_tf32mma<<<dim3(P3 / 128, S_LEN / 128), 256, GEMM_SMEM>>>(hidden, W_pack, proj,
                                                                  S_LEN, P3, HID);
    // 2) RoPE in-place on Q,K
    rope_kernel<<<(S_LEN * NH * 64) / 256, 256>>>(proj, pos_ids);
    // 3) causal flash attention (fp32)
    attn_kernel<<<dim3(NH, S_LEN / 64), 256, ATTN_SMEM>>>(proj, attn);
    // 4) output projection: [2048,4096] @ [4096,4096]^T  (tf32 mma)
    gemm_tf32mma<<<dim3(HID / 128, S_LEN / 128), 256, GEMM_SMEM>>>(attn, W_o, out,
                                                                   S_LEN, HID, HID);
}

// round 5
// speedup vs baseline: 2.6325x; 1.0166x over previous
#include <cuda_runtime.h>
#include <cstdint>
#include <cstddef>

#define S_LEN 2048
#define HID   4096
#define NH    32
#define HD    128
#define P3    12288   // 3*HID
#define NORM  0.08838834764831845f   // 1/sqrt(128)

// ---------------- scratch (no allocations allowed) ----------------
__device__ float g_proj[S_LEN * P3];   // QKV after projection (RoPE applied in-place)
__device__ float g_attn[S_LEN * HID];  // attention output, [s, h*128+d] layout

__device__ __forceinline__ uint32_t f2tf32(float x) {
    uint32_t r;
    asm("cvt.rna.tf32.f32 %0, %1;" : "=r"(r) : "f"(x));
    return r;
}
__device__ __forceinline__ void split_tf32(float x, uint32_t& hi, uint32_t& lo) {
    hi = f2tf32(x);
    lo = f2tf32(x - __uint_as_float(hi));
}

// mma.sync m16n8k8 tf32 (base ISA, works on compute_103)
__device__ __forceinline__ void mma_tf32(float& c0, float& c1, float& c2, float& c3,
                                         uint32_t a0, uint32_t a1, uint32_t a2, uint32_t a3,
                                         uint32_t b0, uint32_t b1) {
    asm volatile(
        "mma.sync.aligned.m16n8k8.row.col.f32.tf32.tf32.f32 "
        "{%0,%1,%2,%3}, {%4,%5,%6,%7}, {%8,%9}, {%0,%1,%2,%3};"
        : "+f"(c0), "+f"(c1), "+f"(c2), "+f"(c3)
        : "r"(a0), "r"(a1), "r"(a2), "r"(a3), "r"(b0), "r"(b1));
}

// ---------------- tf32 mma GEMM: C[M,N] = A[M,K] * B[N,K]^T ----------------
// Block 128x128x32, 256 threads (8 warps), warp tile 64x32.
// SMEM: [row][36] fp32 (stride-36 pad -> conflict-free fragment LDS: bank=(4g+c)%32).
#define GBK    32
#define SROW_G 36
#define GSTG   (128 * SROW_G * 4)          // 18432 B per stage
#define GEMM_SMEM (4 * GSTG)               // A[2] + B[2] = 73728 B

__global__ __launch_bounds__(256, 1) void gemm_tf32mma(const float* __restrict__ A,
                                                       const float* __restrict__ B,
                                                       float* __restrict__ C,
                                                       int M, int N, int K) {
    extern __shared__ float smem[];
    float* As = smem;                       // [2][128][36]
    float* Bs = smem + 2 * 128 * SROW_G;    // [2][128][36]

    const int t = threadIdx.x;
    const int w = t >> 5, lane = t & 31;
    const int wm = w >> 2, wn = w & 3;      // warp grid 2x4 -> 64x32 per warp
    const int g = lane >> 2, cc = lane & 3; // fragment lane decomposition
    const int m0 = blockIdx.y * 128, n0 = blockIdx.x * 128;
    const int KT = K / GBK;

    const int lrow = t >> 3, lc4 = (t & 7) * 4;
    const float* Ab = A + (size_t)(m0 + lrow) * K + lc4;
    const float* Bb = B + (size_t)(n0 + lrow) * K + lc4;
    const size_t rstep = (size_t)32 * K;

    float4 ra[4], rb[4];
#pragma unroll
    for (int i = 0; i < 4; i++) { ra[i] = *(const float4*)(Ab + i * rstep); }
#pragma unroll
    for (int i = 0; i < 4; i++) { rb[i] = *(const float4*)(Bb + i * rstep); }
#pragma unroll
    for (int i = 0; i < 4; i++) {
        uint4 va = {f2tf32(ra[i].x), f2tf32(ra[i].y), f2tf32(ra[i].z), f2tf32(ra[i].w)};
        *(uint4*)&As[(lrow + 32 * i) * SROW_G + lc4] = va;
        uint4 vb = {f2tf32(rb[i].x), f2tf32(rb[i].y), f2tf32(rb[i].z), f2tf32(rb[i].w)};
        *(uint4*)&Bs[(lrow + 32 * i) * SROW_G + lc4] = vb;
    }
    __syncthreads();

    float acc[4][4][4];   // [mt][nt][frag]
#pragma unroll
    for (int mt = 0; mt < 4; mt++)
#pragma unroll
        for (int nt = 0; nt < 4; nt++)
#pragma unroll
            for (int q = 0; q < 4; q++) acc[mt][nt][q] = 0.f;

    for (int kt = 0; kt < KT; kt++) {
        const int cur = kt & 1;
        const bool hasnext = (kt + 1 < KT);
        if (hasnext) {
            const float* Ap = Ab + (size_t)(kt + 1) * GBK;
            const float* Bp = Bb + (size_t)(kt + 1) * GBK;
#pragma unroll
            for (int i = 0; i < 4; i++) ra[i] = *(const float4*)(Ap + i * rstep);
#pragma unroll
            for (int i = 0; i < 4; i++) rb[i] = *(const float4*)(Bp + i * rstep);
        }
        const float* Ac = As + cur * 128 * SROW_G;
        const float* Bc = Bs + cur * 128 * SROW_G;
#pragma unroll
        for (int kc = 0; kc < GBK; kc += 8) {
            uint32_t af[4][4];
#pragma unroll
            for (int mt = 0; mt < 4; mt++) {
                const int r = wm * 64 + mt * 16 + g;
                af[mt][0] = __float_as_uint(Ac[r * SROW_G + kc + cc]);
                af[mt][1] = __float_as_uint(Ac[(r + 8) * SROW_G + kc + cc]);
                af[mt][2] = __float_as_uint(Ac[r * SROW_G + kc + cc + 4]);
                af[mt][3] = __float_as_uint(Ac[(r + 8) * SROW_G + kc + cc + 4]);
            }
            uint32_t bf[4][2];
#pragma unroll
            for (int nt = 0; nt < 4; nt++) {
                const int n = wn * 32 + nt * 8 + g;
                bf[nt][0] = __float_as_uint(Bc[n * SROW_G + kc + cc]);
                bf[nt][1] = __float_as_uint(Bc[n * SROW_G + kc + cc + 4]);
            }
#pragma unroll
            for (int mt = 0; mt < 4; mt++)
#pragma unroll
                for (int nt = 0; nt < 4; nt++)
                    mma_tf32(acc[mt][nt][0], acc[mt][nt][1], acc[mt][nt][2], acc[mt][nt][3],
                             af[mt][0], af[mt][1], af[mt][2], af[mt][3],
                             bf[nt][0], bf[nt][1]);
        }
        __syncthreads();
        if (hasnext) {
            const int nxt = cur ^ 1;
            float* An = As + nxt * 128 * SROW_G;
            float* Bn = Bs + nxt * 128 * SROW_G;
#pragma unroll
            for (int i = 0; i < 4; i++) {
                uint4 va = {f2tf32(ra[i].x), f2tf32(ra[i].y), f2tf32(ra[i].z), f2tf32(ra[i].w)};
                *(uint4*)&An[(lrow + 32 * i) * SROW_G + lc4] = va;
                uint4 vb = {f2tf32(rb[i].x), f2tf32(rb[i].y), f2tf32(rb[i].z), f2tf32(rb[i].w)};
                *(uint4*)&Bn[(lrow + 32 * i) * SROW_G + lc4] = vb;
            }
            __syncthreads();
        }
    }

#pragma unroll
    for (int mt = 0; mt < 4; mt++) {
        const int r = m0 + wm * 64 + mt * 16 + g;
#pragma unroll
        for (int nt = 0; nt < 4; nt++) {
            const int n = n0 + wn * 32 + nt * 8 + 2 * cc;
            *(float2*)&C[(size_t)r * N + n]       = make_float2(acc[mt][nt][0], acc[mt][nt][1]);
            *(float2*)&C[(size_t)(r + 8) * N + n] = make_float2(acc[mt][nt][2], acc[mt][nt][3]);
        }
    }
}

// ---------------- RoPE (in-place on g_proj, Q and K) ----------------
__global__ void rope_kernel(float* __restrict__ proj, const int* __restrict__ pos_ids) {
    int idx = blockIdx.x * blockDim.x + threadIdx.x;   // S*NH*64 threads
    if (idx >= S_LEN * NH * 64) return;
    int d = idx & 63;
    int h = (idx >> 6) & 31;
    int s = idx >> 11;
    int pos = pos_ids[s];

    double inv = exp(-((double)d / 64.0) * 9.210340371976184);  // ln(10000)
    double a = (double)pos * inv;
    const double twopi = 6.283185307179586476925286766559;
    a -= floor(a / twopi) * twopi;
    float sa = sinf((float)a);
    float ca = cosf((float)a);

    size_t base = (size_t)s * P3 + h * HD;
    float q1 = proj[base + d], q2 = proj[base + d + 64];
    proj[base + d]      = q1 * ca - q2 * sa;
    proj[base + d + 64] = q2 * ca + q1 * sa;
    size_t kb = base + HID;
    float k1 = proj[kb + d], k2 = proj[kb + d + 64];
    proj[kb + d]      = k1 * ca - k2 * sa;
    proj[kb + d + 64] = k2 * ca + k1 * sa;
}

// ---------------- Tensor-core flash attention (split-tf32, fp32-accurate) ----------------
// CTA: 128 q-rows, 8 warps (warp w owns rows 16w..16w+15). K-tiles of 64.
// Split-tf32 (hi/lo, 3 MMAs) for QK^T and PV -> ~1e-6 relative error.
#define QPAD 132
#define PPAD 68
#define ATTN_SMEM ((128 * QPAD + 64 * QPAD + 64 * QPAD + 128 * PPAD + 3 * 128) * 4)

__global__ __launch_bounds__(256, 1) void attn_tc(const float* __restrict__ proj,
                                                  float* __restrict__ attn_out) {
    extern __shared__ float sm[];
    float* Qs   = sm;                       // [128][QPAD], pre-scaled by NORM
    float* Ks   = Qs + 128 * QPAD;          // [64][QPAD]
    float* Vs   = Ks + 64 * QPAD;           // [64][QPAD]
    float* Ps   = Vs + 64 * QPAD;           // [128][PPAD]
    float* rowM = Ps + 128 * PPAD;
    float* rowL = rowM + 128;
    float* rowA = rowL + 128;

    const int t = threadIdx.x;
    const int w = t >> 5, lane = t & 31;
    const int g = lane >> 2, cc = lane & 3;
    const int h = blockIdx.x;
    const int qt = 15 - (int)blockIdx.y;    // heavy tiles first
    const int qbase = qt * 128;
    const int qcol = h * HD, kcol = HID + h * HD, vcol = 2 * HID + h * HD;

    // load Q tile (pre-scaled by 1/sqrt(d))
    {
        const int row = t >> 1;
        const int c0 = (t & 1) * 64;
        const float* src = proj + (size_t)(qbase + row) * P3 + qcol + c0;
        float* dst = Qs + row * QPAD + c0;
#pragma unroll
        for (int i = 0; i < 16; i++) {
            float4 v = *(const float4*)(src + i * 4);
            dst[i * 4 + 0] = v.x * NORM; dst[i * 4 + 1] = v.y * NORM;
            dst[i * 4 + 2] = v.z * NORM; dst[i * 4 + 3] = v.w * NORM;
        }
    }
    if (t < 128) { rowM[t] = -3.0e38f; rowL[t] = 0.f; }

    float oacc[16][4];
#pragma unroll
    for (int nt = 0; nt < 16; nt++)
#pragma unroll
        for (int q = 0; q < 4; q++) oacc[nt][q] = 0.f;

    const int nkt = 2 * qt + 2;
    for (int j = 0; j < nkt; j++) {
        __syncthreads();   // previous PV done (and Q load on first iter)
        // load K, V tiles
        {
            const int r = t >> 2;
            const int c0 = (t & 3) * 32;
            const size_t grow = (size_t)(j * 64 + r) * P3;
#pragma unroll
            for (int i = 0; i < 8; i++) {
                *(float4*)(Ks + r * QPAD + c0 + i * 4) =
                    *(const float4*)(proj + grow + kcol + c0 + i * 4);
                *(float4*)(Vs + r * QPAD + c0 + i * 4) =
                    *(const float4*)(proj + grow + vcol + c0 + i * 4);
            }
        }
        __syncthreads();

        // ---- scores: warp computes rows [16w,16w+16) x 64 cols ----
        float sacc[8][4];
#pragma unroll
        for (int nt = 0; nt < 8; nt++)
#pragma unroll
            for (int q = 0; q < 4; q++) sacc[nt][q] = 0.f;

        const float* qr0 = Qs + (w * 16 + g) * QPAD;
        const float* qr1 = qr0 + 8 * QPAD;
#pragma unroll 4
        for (int kc = 0; kc < 16; kc++) {
            uint32_t qh[4], ql[4];
            split_tf32(qr0[kc * 8 + cc],     qh[0], ql[0]);
            split_tf32(qr1[kc * 8 + cc],     qh[1], ql[1]);
            split_tf32(qr0[kc * 8 + cc + 4], qh[2], ql[2]);
            split_tf32(qr1[kc * 8 + cc + 4], qh[3], ql[3]);
#pragma unroll
            for (int nt = 0; nt < 8; nt++) {
                const float* kr = Ks + (nt * 8 + g) * QPAD + kc * 8;
                uint32_t bh0, bl0, bh1, bl1;
                split_tf32(kr[cc],     bh0, bl0);
                split_tf32(kr[cc + 4], bh1, bl1);
                mma_tf32(sacc[nt][0], sacc[nt][1], sacc[nt][2], sacc[nt][3],
                         qh[0], qh[1], qh[2], qh[3], bh0, bh1);
                mma_tf32(sacc[nt][0], sacc[nt][1], sacc[nt][2], sacc[nt][3],
                         qh[0], qh[1], qh[2], qh[3], bl0, bl1);
                mma_tf32(sacc[nt][0], sacc[nt][1], sacc[nt][2], sacc[nt][3],
                         ql[0], ql[1], ql[2], ql[3], bh0, bh1);
            }
        }
        // write scores to Ps with causal mask
        {
            const bool diagt = (j * 64 + 63 > qbase);   // only last two tiles
            const int r0g = qbase + w * 16 + g;
            float* pp0 = Ps + (w * 16 + g) * PPAD;
            float* pp1 = pp0 + 8 * PPAD;
#pragma unroll
            for (int nt = 0; nt < 8; nt++) {
                const int cg = j * 64 + nt * 8 + 2 * cc;
                float v0 = sacc[nt][0], v1 = sacc[nt][1];
                float v2 = sacc[nt][2], v3 = sacc[nt][3];
                if (diagt) {
                    if (cg     > r0g)     v0 = -1.0e9f;
                    if (cg + 1 > r0g)     v1 = -1.0e9f;
                    if (cg     > r0g + 8) v2 = -1.0e9f;
                    if (cg + 1 > r0g + 8) v3 = -1.0e9f;
                }
                pp0[nt * 8 + 2 * cc] = v0; pp0[nt * 8 + 2 * cc + 1] = v1;
                pp1[nt * 8 + 2 * cc] = v2; pp1[nt * 8 + 2 * cc + 1] = v3;
            }
        }
        __syncthreads();

        // ---- online softmax: 2 threads per row ----
        {
            const int row = t >> 1, half = t & 1;
            float* pr = Ps + row * PPAD + half * 32;
            float m = -3.0e38f;
#pragma unroll 8
            for (int i = 0; i < 32; i++) m = fmaxf(m, pr[i]);
            m = fmaxf(m, __shfl_xor_sync(0xFFFFFFFFu, m, 1));
            const float mold = rowM[row];
            const float mnew = fmaxf(mold, m);
            float ssum = 0.f;
#pragma unroll 8
            for (int i = 0; i < 32; i++) {
                float p = __expf(pr[i] - mnew);
                pr[i] = p;
                ssum += p;
            }
            ssum += __shfl_xor_sync(0xFFFFFFFFu, ssum, 1);
            if (half == 0) {
                const float alpha = __expf(mold - mnew);
                rowA[row] = alpha;
                rowL[row] = rowL[row] * alpha + ssum;
                rowM[row] = mnew;
            }
        }
        __syncthreads();

        // ---- PV: O = O*alpha + P @ V ----
        {
            const float al0 = rowA[w * 16 + g], al1 = rowA[w * 16 + 8 + g];
#pragma unroll
            for (int nt = 0; nt < 16; nt++) {
                oacc[nt][0] *= al0; oacc[nt][1] *= al0;
                oacc[nt][2] *= al1; oacc[nt][3] *= al1;
            }
            const float* pr0 = Ps + (w * 16 + g) * PPAD;
            const float* pr1 = pr0 + 8 * PPAD;
#pragma unroll 2
            for (int kc = 0; kc < 8; kc++) {
                uint32_t ph[4], pl[4];
                split_tf32(pr0[kc * 8 + cc],     ph[0], pl[0]);
                split_tf32(pr1[kc * 8 + cc],     ph[1], pl[1]);
                split_tf32(pr0[kc * 8 + cc + 4], ph[2], pl[2]);
                split_tf32(pr1[kc * 8 + cc + 4], ph[3], pl[3]);
#pragma unroll
                for (int nt = 0; nt < 16; nt++) {
                    uint32_t bh0, bl0, bh1, bl1;
                    split_tf32(Vs[(kc * 8 + cc) * QPAD + nt * 8 + g],     bh0, bl0);
                    split_tf32(Vs[(kc * 8 + cc + 4) * QPAD + nt * 8 + g], bh1, bl1);
                    mma_tf32(oacc[nt][0], oacc[nt][1], oacc[nt][2], oacc[nt][3],
                             ph[0], ph[1], ph[2], ph[3], bh0, bh1);
                    mma_tf32(oacc[nt][0], oacc[nt][1], oacc[nt][2], oacc[nt][3],
                             ph[0], ph[1], ph[2], ph[3], bl0, bl1);
                    mma_tf32(oacc[nt][0], oacc[nt][1], oacc[nt][2], oacc[nt][3],
                             pl[0], pl[1], pl[2], pl[3], bh0, bh1);
                }
            }
        }
    }

    // epilogue: O /= L, write [s][h*128+d]
    {
        const float il0 = 1.0f / rowL[w * 16 + g];
        const float il1 = 1.0f / rowL[w * 16 + 8 + g];
        const size_t base0 = (size_t)(qbase + w * 16 + g) * HID + h * HD + 2 * cc;
#pragma unroll
        for (int nt = 0; nt < 16; nt++) {
            *(float2*)(attn_out + base0 + nt * 8) =
                make_float2(oacc[nt][0] * il0, oacc[nt][1] * il0);
            *(float2*)(attn_out + base0 + 8 * HID + nt * 8) =
                make_float2(oacc[nt][2] * il1, oacc[nt][3] * il1);
        }
    }
}

// ---------------- launch ----------------
extern "C" void kernel_launch(void* const* d_in, const int* in_sizes, int n_in,
                              void* d_out, int out_size) {
    (void)in_sizes; (void)n_in; (void)out_size;
    const float* hidden  = (const float*)d_in[0];
    // d_in[1] = attention_mask: deterministic causal -> applied analytically
    const int*   pos_ids = (const int*)d_in[2];
    const float* W_pack  = (const float*)d_in[3];
    const float* W_o     = (const float*)d_in[4];
    float* out = (float*)d_out;

    float *proj = nullptr, *attn = nullptr;
    cudaGetSymbolAddress((void**)&proj, g_proj);
    cudaGetSymbolAddress((void**)&attn, g_attn);
    cudaFuncSetAttribute(gemm_tf32mma, cudaFuncAttributeMaxDynamicSharedMemorySize, GEMM_SMEM);
    cudaFuncSetAttribute(attn_tc, cudaFuncAttributeMaxDynamicSharedMemorySize, ATTN_SMEM);

    // 1) QKV projection: [2048,4096] @ [12288,4096]^T  (tf32 mma)
    gemm_tf32mma<<<dim3(P3 / 128, S_LEN / 128), 256, GEMM_SMEM>>>(hidden, W_pack, proj,
                                                                  S_LEN, P3, HID);
    // 2) RoPE in-place on Q,K
    rope_kernel<<<(S_LEN * NH * 64) / 256, 256>>>(proj, pos_ids);
    // 3) causal flash attention (split-tf32 tensor cores)
    attn_tc<<<dim3(NH, S_LEN / 128), 256, ATTN_SMEM>>>(proj, attn);
    // 4) output projection: [2048,4096] @ [4096,4096]^T  (tf32 mma)
    gemm_tf32mma<<<dim3(HID / 128, S_LEN / 128), 256, GEMM_SMEM>>>(attn, W_o, out,
                                                                   S_LEN, HID, HID);
}

// round 6
// speedup vs baseline: 3.2757x; 1.2443x over previous
#include <cuda_runtime.h>
#include <cstdint>
#include <cstddef>

#define S_LEN 2048
#define HID   4096
#define NH    32
#define HD    128
#define P3    12288   // 3*HID
#define NORM  0.08838834764831845f   // 1/sqrt(128)

// ---------------- scratch (no allocations allowed) ----------------
__device__ float g_proj[S_LEN * P3];   // QKV after projection (RoPE applied in-place)
__device__ float g_attn[S_LEN * HID];  // attention output, [s, h*128+d] layout

__device__ __forceinline__ uint32_t f2tf32(float x) {
    uint32_t r;
    asm("cvt.rna.tf32.f32 %0, %1;" : "=r"(r) : "f"(x));
    return r;
}

// mma.sync m16n8k8 tf32 (base ISA)
__device__ __forceinline__ void mma_tf32(float& c0, float& c1, float& c2, float& c3,
                                         uint32_t a0, uint32_t a1, uint32_t a2, uint32_t a3,
                                         uint32_t b0, uint32_t b1) {
    asm volatile(
        "mma.sync.aligned.m16n8k8.row.col.f32.tf32.tf32.f32 "
        "{%0,%1,%2,%3}, {%4,%5,%6,%7}, {%8,%9}, {%0,%1,%2,%3};"
        : "+f"(c0), "+f"(c1), "+f"(c2), "+f"(c3)
        : "r"(a0), "r"(a1), "r"(a2), "r"(a3), "r"(b0), "r"(b1));
}

// mma.sync m16n8k16 bf16 (base ISA)
__device__ __forceinline__ void mma_bf16(float& c0, float& c1, float& c2, float& c3,
                                         uint32_t a0, uint32_t a1, uint32_t a2, uint32_t a3,
                                         uint32_t b0, uint32_t b1) {
    asm volatile(
        "mma.sync.aligned.m16n8k16.row.col.f32.bf16.bf16.f32 "
        "{%0,%1,%2,%3}, {%4,%5,%6,%7}, {%8,%9}, {%0,%1,%2,%3};"
        : "+f"(c0), "+f"(c1), "+f"(c2), "+f"(c3)
        : "r"(a0), "r"(a1), "r"(a2), "r"(a3), "r"(b0), "r"(b1));
}

// split x into hi(bf16) + lo(bf16); pack two adjacent k-elements per b32
__device__ __forceinline__ void split_pair(float x0, float x1, uint32_t& hp, uint32_t& lp) {
    uint16_t h0, h1, l0, l1;
    asm("cvt.rn.bf16.f32 %0, %1;" : "=h"(h0) : "f"(x0));
    asm("cvt.rn.bf16.f32 %0, %1;" : "=h"(h1) : "f"(x1));
    float r0 = x0 - __uint_as_float((uint32_t)h0 << 16);
    float r1 = x1 - __uint_as_float((uint32_t)h1 << 16);
    asm("cvt.rn.bf16.f32 %0, %1;" : "=h"(l0) : "f"(r0));
    asm("cvt.rn.bf16.f32 %0, %1;" : "=h"(l1) : "f"(r1));
    asm("mov.b32 %0, {%1, %2};" : "=r"(hp) : "h"(h0), "h"(h1));
    asm("mov.b32 %0, {%1, %2};" : "=r"(lp) : "h"(l0), "h"(l1));
}

// ---------------- tf32 mma GEMM: C[M,N] = A[M,K] * B[N,K]^T (unchanged) ----------------
#define GBK    32
#define SROW_G 36
#define GSTG   (128 * SROW_G * 4)
#define GEMM_SMEM (4 * GSTG)

__global__ __launch_bounds__(256, 1) void gemm_tf32mma(const float* __restrict__ A,
                                                       const float* __restrict__ B,
                                                       float* __restrict__ C,
                                                       int M, int N, int K) {
    extern __shared__ float smem[];
    float* As = smem;
    float* Bs = smem + 2 * 128 * SROW_G;

    const int t = threadIdx.x;
    const int w = t >> 5, lane = t & 31;
    const int wm = w >> 2, wn = w & 3;
    const int g = lane >> 2, cc = lane & 3;
    const int m0 = blockIdx.y * 128, n0 = blockIdx.x * 128;
    const int KT = K / GBK;

    const int lrow = t >> 3, lc4 = (t & 7) * 4;
    const float* Ab = A + (size_t)(m0 + lrow) * K + lc4;
    const float* Bb = B + (size_t)(n0 + lrow) * K + lc4;
    const size_t rstep = (size_t)32 * K;

    float4 ra[4], rb[4];
#pragma unroll
    for (int i = 0; i < 4; i++) { ra[i] = *(const float4*)(Ab + i * rstep); }
#pragma unroll
    for (int i = 0; i < 4; i++) { rb[i] = *(const float4*)(Bb + i * rstep); }
#pragma unroll
    for (int i = 0; i < 4; i++) {
        uint4 va = {f2tf32(ra[i].x), f2tf32(ra[i].y), f2tf32(ra[i].z), f2tf32(ra[i].w)};
        *(uint4*)&As[(lrow + 32 * i) * SROW_G + lc4] = va;
        uint4 vb = {f2tf32(rb[i].x), f2tf32(rb[i].y), f2tf32(rb[i].z), f2tf32(rb[i].w)};
        *(uint4*)&Bs[(lrow + 32 * i) * SROW_G + lc4] = vb;
    }
    __syncthreads();

    float acc[4][4][4];
#pragma unroll
    for (int mt = 0; mt < 4; mt++)
#pragma unroll
        for (int nt = 0; nt < 4; nt++)
#pragma unroll
            for (int q = 0; q < 4; q++) acc[mt][nt][q] = 0.f;

    for (int kt = 0; kt < KT; kt++) {
        const int cur = kt & 1;
        const bool hasnext = (kt + 1 < KT);
        if (hasnext) {
            const float* Ap = Ab + (size_t)(kt + 1) * GBK;
            const float* Bp = Bb + (size_t)(kt + 1) * GBK;
#pragma unroll
            for (int i = 0; i < 4; i++) ra[i] = *(const float4*)(Ap + i * rstep);
#pragma unroll
            for (int i = 0; i < 4; i++) rb[i] = *(const float4*)(Bp + i * rstep);
        }
        const float* Ac = As + cur * 128 * SROW_G;
        const float* Bc = Bs + cur * 128 * SROW_G;
#pragma unroll
        for (int kc = 0; kc < GBK; kc += 8) {
            uint32_t af[4][4];
#pragma unroll
            for (int mt = 0; mt < 4; mt++) {
                const int r = wm * 64 + mt * 16 + g;
                af[mt][0] = __float_as_uint(Ac[r * SROW_G + kc + cc]);
                af[mt][1] = __float_as_uint(Ac[(r + 8) * SROW_G + kc + cc]);
                af[mt][2] = __float_as_uint(Ac[r * SROW_G + kc + cc + 4]);
                af[mt][3] = __float_as_uint(Ac[(r + 8) * SROW_G + kc + cc + 4]);
            }
            uint32_t bf[4][2];
#pragma unroll
            for (int nt = 0; nt < 4; nt++) {
                const int n = wn * 32 + nt * 8 + g;
                bf[nt][0] = __float_as_uint(Bc[n * SROW_G + kc + cc]);
                bf[nt][1] = __float_as_uint(Bc[n * SROW_G + kc + cc + 4]);
            }
#pragma unroll
            for (int mt = 0; mt < 4; mt++)
#pragma unroll
                for (int nt = 0; nt < 4; nt++)
                    mma_tf32(acc[mt][nt][0], acc[mt][nt][1], acc[mt][nt][2], acc[mt][nt][3],
                             af[mt][0], af[mt][1], af[mt][2], af[mt][3],
                             bf[nt][0], bf[nt][1]);
        }
        __syncthreads();
        if (hasnext) {
            const int nxt = cur ^ 1;
            float* An = As + nxt * 128 * SROW_G;
            float* Bn = Bs + nxt * 128 * SROW_G;
#pragma unroll
            for (int i = 0; i < 4; i++) {
                uint4 va = {f2tf32(ra[i].x), f2tf32(ra[i].y), f2tf32(ra[i].z), f2tf32(ra[i].w)};
                *(uint4*)&An[(lrow + 32 * i) * SROW_G + lc4] = va;
                uint4 vb = {f2tf32(rb[i].x), f2tf32(rb[i].y), f2tf32(rb[i].z), f2tf32(rb[i].w)};
                *(uint4*)&Bn[(lrow + 32 * i) * SROW_G + lc4] = vb;
            }
            __syncthreads();
        }
    }

#pragma unroll
    for (int mt = 0; mt < 4; mt++) {
        const int r = m0 + wm * 64 + mt * 16 + g;
#pragma unroll
        for (int nt = 0; nt < 4; nt++) {
            const int n = n0 + wn * 32 + nt * 8 + 2 * cc;
            *(float2*)&C[(size_t)r * N + n]       = make_float2(acc[mt][nt][0], acc[mt][nt][1]);
            *(float2*)&C[(size_t)(r + 8) * N + n] = make_float2(acc[mt][nt][2], acc[mt][nt][3]);
        }
    }
}

// ---------------- RoPE v2: one block per sequence position, smem trig table ----------------
__global__ __launch_bounds__(256) void rope2_kernel(float* __restrict__ proj,
                                                    const int* __restrict__ pos_ids) {
    __shared__ float ca[64], sa[64];
    const int s = blockIdx.x;
    const int t = threadIdx.x;
    if (t < 64) {
        const int pos = pos_ids[s];
        double inv = exp(-((double)t / 64.0) * 9.210340371976184);  // ln(10000)
        double a = (double)pos * inv;
        const double twopi = 6.283185307179586476925286766559;
        a -= floor(a / twopi) * twopi;
        sa[t] = sinf((float)a);
        ca[t] = cosf((float)a);
    }
    __syncthreads();
    // 4096 rotation pairs: p<2048 -> Q, else K
    float* base = proj + (size_t)s * P3;
#pragma unroll
    for (int it = 0; it < 16; it++) {
        const int p = t + it * 256;
        const int d = p & 63;
        const int hh = (p >> 6) & 31;
        float* ptr = base + ((p >> 11) ? HID : 0) + hh * HD + d;
        const float x1 = ptr[0], x2 = ptr[64];
        const float c = ca[d], sn = sa[d];
        ptr[0]  = x1 * c - x2 * sn;
        ptr[64] = x2 * c + x1 * sn;
    }
}

// ---------------- bf16-split tensor-core flash attention ----------------
// CTA: 128 q-rows, 8 warps (warp owns 16 rows); k-tiles of 64.
// All operands pre-split (hi,lo bf16) in SMEM; hh+hl+lh m16n8k16 MMAs => ~1e-5 error.
#define QSTR 136   // bf16 units per row (128 + 8 pad) -> frag bank (4g+cc)%32, conflict-free
#define VSTR 72    // bf16 units per row (64 + 8 pad)
#define SSTR 65    // fp32 stride for raw scores
// byte offsets
#define OFF_QH  0
#define OFF_QL  (OFF_QH + 128 * QSTR * 2)     // 34816
#define OFF_KH  (OFF_QL + 128 * QSTR * 2)     // 69632
#define OFF_KL  (OFF_KH + 64 * QSTR * 2)      // 87040
#define OFF_VTH (OFF_KL + 64 * QSTR * 2)      // 104448
#define OFF_VTL (OFF_VTH + 128 * VSTR * 2)    // 122880
#define OFF_SF  (OFF_VTL + 128 * VSTR * 2)    // 141312
#define OFF_PH  (OFF_SF + 128 * SSTR * 4)     // 174592
#define OFF_PL  (OFF_PH + 128 * VSTR * 2)     // 193024
#define OFF_ST  (OFF_PL + 128 * VSTR * 2)     // 211456
#define ATTN2_SMEM (OFF_ST + 3 * 128 * 4)     // 212992

__global__ __launch_bounds__(256, 1) void attn_bf16(const float* __restrict__ proj,
                                                    float* __restrict__ attn_out) {
    extern __shared__ char smraw[];
    uint32_t* Qh  = (uint32_t*)(smraw + OFF_QH);    // word stride 68
    uint32_t* Ql  = (uint32_t*)(smraw + OFF_QL);
    uint32_t* Kh  = (uint32_t*)(smraw + OFF_KH);
    uint32_t* Kl  = (uint32_t*)(smraw + OFF_KL);
    uint32_t* Vth = (uint32_t*)(smraw + OFF_VTH);   // word stride 36, [dim][kv]
    uint32_t* Vtl = (uint32_t*)(smraw + OFF_VTL);
    float*    Sf  = (float*)(smraw + OFF_SF);       // [128][65]
    uint32_t* Ph  = (uint32_t*)(smraw + OFF_PH);    // word stride 36
    uint32_t* Pl  = (uint32_t*)(smraw + OFF_PL);
    float*    rowM = (float*)(smraw + OFF_ST);
    float*    rowL = rowM + 128;
    float*    rowA = rowL + 128;

    const int t = threadIdx.x;
    const int w = t >> 5, lane = t & 31;
    const int g = lane >> 2, cc = lane & 3;
    const int h = blockIdx.x;
    const int qt = 15 - (int)blockIdx.y;   // heavy tiles first
    const int qbase = qt * 128;
    const int qcol = h * HD, kcol = HID + h * HD, vcol = 2 * HID + h * HD;

    // ---- load + split Q (scaled by NORM) ----
    {
        const int row = t >> 1;
        const int c0 = (t & 1) * 64;
        const float* src = proj + (size_t)(qbase + row) * P3 + qcol + c0;
        uint32_t* qh = Qh + row * 68 + (c0 >> 1);
        uint32_t* ql = Ql + row * 68 + (c0 >> 1);
#pragma unroll
        for (int i = 0; i < 16; i++) {
            float4 v = *(const float4*)(src + i * 4);
            uint32_t hp, lp;
            split_pair(v.x * NORM, v.y * NORM, hp, lp);
            qh[2 * i] = hp; ql[2 * i] = lp;
            split_pair(v.z * NORM, v.w * NORM, hp, lp);
            qh[2 * i + 1] = hp; ql[2 * i + 1] = lp;
        }
    }
    if (t < 128) { rowM[t] = -3.0e38f; rowL[t] = 0.f; }

    float oacc[16][4];
#pragma unroll
    for (int nt = 0; nt < 16; nt++)
#pragma unroll
        for (int q = 0; q < 4; q++) oacc[nt][q] = 0.f;

    const int nkt = 2 * qt + 2;
    for (int j = 0; j < nkt; j++) {
        __syncthreads();   // prev PV done / Q split visible
        // ---- load + split K ----
        {
            const int r = t >> 2;
            const int c0 = (t & 3) * 32;
            const float* src = proj + (size_t)(j * 64 + r) * P3 + kcol + c0;
            uint32_t* kh = Kh + r * 68 + (c0 >> 1);
            uint32_t* kl = Kl + r * 68 + (c0 >> 1);
#pragma unroll
            for (int i = 0; i < 8; i++) {
                float4 v = *(const float4*)(src + i * 4);
                uint32_t hp, lp;
                split_pair(v.x, v.y, hp, lp);
                kh[2 * i] = hp; kl[2 * i] = lp;
                split_pair(v.z, v.w, hp, lp);
                kh[2 * i + 1] = hp; kl[2 * i + 1] = lp;
            }
        }
        // ---- load + split + transpose V: Vt[dim][kv] ----
        {
            const int c = (t & 31) + ((t >> 5) & 3) * 32;   // dim 0..127
            const int rp0 = (t >> 7) * 16;                  // row-pair start
            const float* vsrc = proj + (size_t)(j * 64) * P3 + vcol + c;
#pragma unroll
            for (int it = 0; it < 16; it++) {
                const int rp = rp0 + it;
                const float v0 = vsrc[(size_t)(2 * rp) * P3];
                const float v1 = vsrc[(size_t)(2 * rp + 1) * P3];
                uint32_t hp, lp;
                split_pair(v0, v1, hp, lp);
                Vth[c * 36 + rp] = hp;
                Vtl[c * 36 + rp] = lp;
            }
        }
        __syncthreads();

        // ---- scores: warp rows [16w,16w+16) x 64 cols ----
        float sacc[8][4];
#pragma unroll
        for (int nt = 0; nt < 8; nt++)
#pragma unroll
            for (int q = 0; q < 4; q++) sacc[nt][q] = 0.f;

        const uint32_t* q0 = Qh + (w * 16 + g) * 68;
        const uint32_t* q1 = q0 + 8 * 68;
        const uint32_t* q0l = Ql + (w * 16 + g) * 68;
        const uint32_t* q1l = q0l + 8 * 68;
#pragma unroll
        for (int kc = 0; kc < 8; kc++) {
            const int kw = kc * 8;
            uint32_t ah0 = q0[kw + cc], ah1 = q1[kw + cc];
            uint32_t ah2 = q0[kw + cc + 4], ah3 = q1[kw + cc + 4];
            uint32_t al0 = q0l[kw + cc], al1 = q1l[kw + cc];
            uint32_t al2 = q0l[kw + cc + 4], al3 = q1l[kw + cc + 4];
#pragma unroll
            for (int nt = 0; nt < 8; nt++) {
                const int nw = (nt * 8 + g) * 68 + kw;
                uint32_t bh0 = Kh[nw + cc], bh1 = Kh[nw + cc + 4];
                uint32_t bl0 = Kl[nw + cc], bl1 = Kl[nw + cc + 4];
                mma_bf16(sacc[nt][0], sacc[nt][1], sacc[nt][2], sacc[nt][3],
                         ah0, ah1, ah2, ah3, bh0, bh1);
                mma_bf16(sacc[nt][0], sacc[nt][1], sacc[nt][2], sacc[nt][3],
                         ah0, ah1, ah2, ah3, bl0, bl1);
                mma_bf16(sacc[nt][0], sacc[nt][1], sacc[nt][2], sacc[nt][3],
                         al0, al1, al2, al3, bh0, bh1);
            }
        }
        // write scores with causal mask
        {
            const bool diagt = (j * 64 + 63 > qbase);
            const int r0g = qbase + w * 16 + g;
            float* s0 = Sf + (w * 16 + g) * SSTR;
            float* s1 = s0 + 8 * SSTR;
#pragma unroll
            for (int nt = 0; nt < 8; nt++) {
                const int cg = j * 64 + nt * 8 + 2 * cc;
                float v0 = sacc[nt][0], v1 = sacc[nt][1];
                float v2 = sacc[nt][2], v3 = sacc[nt][3];
                if (diagt) {
                    if (cg     > r0g)     v0 = -1.0e9f;
                    if (cg + 1 > r0g)     v1 = -1.0e9f;
                    if (cg     > r0g + 8) v2 = -1.0e9f;
                    if (cg + 1 > r0g + 8) v3 = -1.0e9f;
                }
                s0[nt * 8 + 2 * cc] = v0; s0[nt * 8 + 2 * cc + 1] = v1;
                s1[nt * 8 + 2 * cc] = v2; s1[nt * 8 + 2 * cc + 1] = v3;
            }
        }
        __syncthreads();

        // ---- online softmax (2 threads/row), write split P ----
        {
            const int row = t >> 1, half = t & 1;
            const float* pr = Sf + row * SSTR + half * 32;
            float m = -3.0e38f;
#pragma unroll 8
            for (int i = 0; i < 32; i++) m = fmaxf(m, pr[i]);
            m = fmaxf(m, __shfl_xor_sync(0xFFFFFFFFu, m, 1));
            const float mold = rowM[row];
            const float mnew = fmaxf(mold, m);
            float ssum = 0.f;
            uint32_t* ph = Ph + row * 36 + half * 16;
            uint32_t* pl = Pl + row * 36 + half * 16;
#pragma unroll 4
            for (int i = 0; i < 16; i++) {
                const float p0 = __expf(pr[2 * i] - mnew);
                const float p1 = __expf(pr[2 * i + 1] - mnew);
                ssum += p0 + p1;
                uint32_t hp, lp;
                split_pair(p0, p1, hp, lp);
                ph[i] = hp; pl[i] = lp;
            }
            ssum += __shfl_xor_sync(0xFFFFFFFFu, ssum, 1);
            if (half == 0) {
                const float alpha = __expf(mold - mnew);
                rowA[row] = alpha;
                rowL[row] = rowL[row] * alpha + ssum;
                rowM[row] = mnew;
            }
        }
        __syncthreads();

        // ---- PV: O = O*alpha + P @ V ----
        {
            const float al0 = rowA[w * 16 + g], al1 = rowA[w * 16 + 8 + g];
#pragma unroll
            for (int nt = 0; nt < 16; nt++) {
                oacc[nt][0] *= al0; oacc[nt][1] *= al0;
                oacc[nt][2] *= al1; oacc[nt][3] *= al1;
            }
            const uint32_t* p0 = Ph + (w * 16 + g) * 36;
            const uint32_t* p1 = p0 + 8 * 36;
            const uint32_t* p0l = Pl + (w * 16 + g) * 36;
            const uint32_t* p1l = p0l + 8 * 36;
#pragma unroll
            for (int kc = 0; kc < 4; kc++) {
                const int kw = kc * 8;
                uint32_t ah0 = p0[kw + cc], ah1 = p1[kw + cc];
                uint32_t ah2 = p0[kw + cc + 4], ah3 = p1[kw + cc + 4];
                uint32_t al0f = p0l[kw + cc], al1f = p1l[kw + cc];
                uint32_t al2f = p0l[kw + cc + 4], al3f = p1l[kw + cc + 4];
#pragma unroll
                for (int nt = 0; nt < 16; nt++) {
                    const int nw = (nt * 8 + g) * 36 + kw;
                    uint32_t bh0 = Vth[nw + cc], bh1 = Vth[nw + cc + 4];
                    uint32_t bl0 = Vtl[nw + cc], bl1 = Vtl[nw + cc + 4];
                    mma_bf16(oacc[nt][0], oacc[nt][1], oacc[nt][2], oacc[nt][3],
                             ah0, ah1, ah2, ah3, bh0, bh1);
                    mma_bf16(oacc[nt][0], oacc[nt][1], oacc[nt][2], oacc[nt][3],
                             ah0, ah1, ah2, ah3, bl0, bl1);
                    mma_bf16(oacc[nt][0], oacc[nt][1], oacc[nt][2], oacc[nt][3],
                             al0f, al1f, al2f, al3f, bh0, bh1);
                }
            }
        }
    }

    // ---- epilogue: O /= L, write [s][h*128+d] ----
    {
        const float il0 = 1.0f / rowL[w * 16 + g];
        const float il1 = 1.0f / rowL[w * 16 + 8 + g];
        const size_t base0 = (size_t)(qbase + w * 16 + g) * HID + h * HD + 2 * cc;
#pragma unroll
        for (int nt = 0; nt < 16; nt++) {
            *(float2*)(attn_out + base0 + nt * 8) =
                make_float2(oacc[nt][0] * il0, oacc[nt][1] * il0);
            *(float2*)(attn_out + base0 + 8 * HID + nt * 8) =
                make_float2(oacc[nt][2] * il1, oacc[nt][3] * il1);
        }
    }
}

// ---------------- launch ----------------
extern "C" void kernel_launch(void* const* d_in, const int* in_sizes, int n_in,
                              void* d_out, int out_size) {
    (void)in_sizes; (void)n_in; (void)out_size;
    const float* hidden  = (const float*)d_in[0];
    // d_in[1] = attention_mask: deterministic causal -> applied analytically
    const int*   pos_ids = (const int*)d_in[2];
    const float* W_pack  = (const float*)d_in[3];
    const float* W_o     = (const float*)d_in[4];
    float* out = (float*)d_out;

    float *proj = nullptr, *attn = nullptr;
    cudaGetSymbolAddress((void**)&proj, g_proj);
    cudaGetSymbolAddress((void**)&attn, g_attn);
    cudaFuncSetAttribute(gemm_tf32mma, cudaFuncAttributeMaxDynamicSharedMemorySize, GEMM_SMEM);
    cudaFuncSetAttribute(attn_bf16, cudaFuncAttributeMaxDynamicSharedMemorySize, ATTN2_SMEM);

    // 1) QKV projection: [2048,4096] @ [12288,4096]^T  (tf32 mma)
    gemm_tf32mma<<<dim3(P3 / 128, S_LEN / 128), 256, GEMM_SMEM>>>(hidden, W_pack, proj,
                                                                  S_LEN, P3, HID);
    // 2) RoPE in-place on Q,K
    rope2_kernel<<<S_LEN, 256>>>(proj, pos_ids);
    // 3) causal flash attention (bf16-split tensor cores, fp32-accurate)
    attn_bf16<<<dim3(NH, S_LEN / 128), 256, ATTN2_SMEM>>>(proj, attn);
    // 4) output projection: [2048,4096] @ [4096,4096]^T  (tf32 mma)
    gemm_tf32mma<<<dim3(HID / 128, S_LEN / 128), 256, GEMM_SMEM>>>(attn, W_o, out,
                                                                   S_LEN, HID, HID);
}